// round 6
// baseline (speedup 1.0000x reference)
#include <cuda_runtime.h>
#include <mma.h>
#include <cstdint>
#include <math.h>

using namespace nvcuda;

#define BC    2
#define LSEQ  2048
#define HIDD  1024
#define NH    16
#define HD    64
#define PFF   4096
#define MROWS (BC * LSEQ)
#define ATT_ELEMS ((size_t)BC * NH * LSEQ * LSEQ)

// ---------------- device scratch ----------------
__device__ float g_q   [MROWS * HIDD];
__device__ float g_k   [MROWS * HIDD];
__device__ float g_v   [MROWS * HIDD];
__device__ float g_ao  [MROWS * HIDD];
__device__ float g_h   [MROWS * HIDD];
__device__ float g_hr  [MROWS * HIDD];
__device__ float g_ffn [(size_t)MROWS * PFF];
__device__ float g_sc  [ATT_ELEMS];
__device__ float g_wt  [16 * 1024 * 1024];   // RN-rounded weights, concatenated
__device__ float g_tgtr[MROWS * HIDD];
__device__ float g_encr[MROWS * HIDD];

// ---------------- helpers ----------------
__device__ __forceinline__ void cp16(uint32_t dst, const float* src) {
    asm volatile("cp.async.cg.shared.global [%0], [%1], 16;"
        :: "r"(dst), "l"(__cvta_generic_to_global(src)));
}
__device__ __forceinline__ uint32_t smem_u32(const void* p) {
    uint32_t a;
    asm("{ .reg .u64 t; cvta.to.shared.u64 t, %1; cvt.u32.u64 %0, t; }"
        : "=r"(a) : "l"(p));
    return a;
}
__device__ __forceinline__ float rn32(float x) {
    unsigned u;
    asm("cvt.rna.tf32.f32 %0, %1;" : "=r"(u) : "f"(x));
    return __uint_as_float(u);
}

// ---------------------------------------------------------------------------
// wmma tf32 GEMM: D[128 x NT] = A[128,K] @ B  (A row-major K-major)
// BT=0: B row-major [K][N] (weights / V).  BT=1: B K-major [N][K] (scores K^T).
// MODE 1: attn-layout out + bias + RN-round   (cross-Q proj)
// MODE 2: relu + bias + RN-round              (FFN up)
// MODE 3: bias + residual, row-major out      (out projections / FFN down)
// MODE 5: scores: *0.125 + mask, batched
// MODE 6: PV out -> O[b*LSEQ+q][h*64+d] + RN-round, batched (NT=64, CVTA=1)
// MODE 7: fused self-QKV (3 segs -> q,k,v attn layout)
// MODE 8: fused cross-KV (2 segs -> k,v attn layout)
// ---------------------------------------------------------------------------
template<int MODE, int NT, int BT, int CVTA, int MINB, int STAGES>
__global__ void __launch_bounds__(256, MINB)
tc_gemm(const float* __restrict__ A, const float* __restrict__ B,
        const float* __restrict__ bias0, const float* __restrict__ bias1,
        const float* __restrict__ bias2, const float* __restrict__ Rres,
        const int* __restrict__ mask,
        float* __restrict__ C0, float* __restrict__ C1, float* __restrict__ C2,
        int K, int lda, int ldb, int ncols,
        long long aBatch, long long bBatch)
{
    constexpr int WY  = (NT >= 128) ? 2 : 4;
    constexpr int WX  = 8 / WY;
    constexpr int WTM = 128 / WY;
    constexpr int WTN = NT / WX;
    constexpr int FM  = WTM / 16;
    constexpr int FN  = WTN / 16;
    constexpr int ABYTES = 128 * 36 * 4;
    constexpr int BBYTES = BT ? NT * 36 * 4 : 32 * (NT + 4) * 4;
    constexpr int CHB = ABYTES + BBYTES;
    constexpr int STG_R = NT + 4;

    extern __shared__ float sm[];
    const uint32_t sb = smem_u32(sm);
    const int t = threadIdx.x, w = t >> 5;
    const int wy = w % WY, wx = w / WY;
    const int m0 = blockIdx.y * 128, n0 = blockIdx.x * NT;
    const int z  = blockIdx.z;

    const float* Ab = A + (size_t)z * aBatch;
    const float* Bb;
    if (MODE == 7 || MODE == 8)
        Bb = B + (size_t)(n0 >> 10) * 1048576 + (n0 & 1023);
    else if (BT == 1)
        Bb = B + (size_t)z * bBatch;
    else
        Bb = B + (size_t)z * bBatch + n0;

    wmma::fragment<wmma::accumulator, 16, 16, 8, float> cf[FM][FN];
#pragma unroll
    for (int i = 0; i < FM; i++)
#pragma unroll
        for (int j = 0; j < FN; j++) wmma::fill_fragment(cf[i][j], 0.0f);

    auto load_chunk = [&](int ci, int s) {
        const int k0 = ci * 32;
        const uint32_t abase = sb + (uint32_t)(s * CHB);
#pragma unroll
        for (int j = 0; j < 4; j++) {
            int id = j * 256 + t, row = id >> 3, cc = id & 7;
            cp16(abase + (uint32_t)(row * 36 + cc * 4) * 4u,
                 Ab + (size_t)(m0 + row) * lda + k0 + cc * 4);
        }
        const uint32_t bbase = abase + ABYTES;
        if (BT == 1) {
#pragma unroll
            for (int j = 0; j < NT / 32; j++) {
                int id = j * 256 + t, row = id >> 3, cc = id & 7;
                cp16(bbase + (uint32_t)(row * 36 + cc * 4) * 4u,
                     Bb + (size_t)(n0 + row) * ldb + k0 + cc * 4);
            }
        } else {
#pragma unroll
            for (int j = 0; j < NT / 32; j++) {
                int id = j * 256 + t, row = id / (NT / 4), c4 = id % (NT / 4);
                cp16(bbase + (uint32_t)(row * (NT + 4) + c4 * 4) * 4u,
                     Bb + (size_t)(k0 + row) * ldb + c4 * 4);
            }
        }
        asm volatile("cp.async.commit_group;");
    };

    const int nch = K / 32;
#pragma unroll
    for (int s = 0; s < STAGES - 1; s++)
        if (s < nch) load_chunk(s, s);

    for (int i = 0; i < nch; i++) {
        if (i + STAGES - 1 < nch) load_chunk(i + STAGES - 1, (i + STAGES - 1) % STAGES);
        else asm volatile("cp.async.commit_group;");
        if (STAGES == 4) asm volatile("cp.async.wait_group 3;");
        else             asm volatile("cp.async.wait_group 2;");
        __syncthreads();
        const float* Ast = sm + (i % STAGES) * (CHB / 4);
        const float* Bst = Ast + ABYTES / 4;
#pragma unroll
        for (int ks = 0; ks < 4; ks++) {
            wmma::fragment<wmma::matrix_a, 16, 16, 8, wmma::precision::tf32, wmma::row_major> af[FM];
#pragma unroll
            for (int fm = 0; fm < FM; fm++) {
                wmma::load_matrix_sync(af[fm], Ast + (wy * WTM + fm * 16) * 36 + ks * 8, 36);
                if (CVTA) {
#pragma unroll
                    for (int e = 0; e < af[fm].num_elements; e++)
                        af[fm].x[e] = wmma::__float_to_tf32(af[fm].x[e]);
                }
            }
            if (BT == 1) {
#pragma unroll
                for (int fn = 0; fn < FN; fn++) {
                    wmma::fragment<wmma::matrix_b, 16, 16, 8, wmma::precision::tf32, wmma::col_major> bf;
                    wmma::load_matrix_sync(bf, Bst + (wx * WTN + fn * 16) * 36 + ks * 8, 36);
#pragma unroll
                    for (int fm = 0; fm < FM; fm++)
                        wmma::mma_sync(cf[fm][fn], af[fm], bf, cf[fm][fn]);
                }
            } else {
#pragma unroll
                for (int fn = 0; fn < FN; fn++) {
                    wmma::fragment<wmma::matrix_b, 16, 16, 8, wmma::precision::tf32, wmma::row_major> bf;
                    wmma::load_matrix_sync(bf, Bst + ks * 8 * (NT + 4) + wx * WTN + fn * 16, NT + 4);
#pragma unroll
                    for (int fm = 0; fm < FM; fm++)
                        wmma::mma_sync(cf[fm][fn], af[fm], bf, cf[fm][fn]);
                }
            }
        }
        __syncthreads();
    }
    __syncthreads();

    // ---- epilogue routing (block-uniform) ----
    int em = (MODE == 7 || MODE == 8) ? 1 : MODE;
    int nrel = n0;
    const float* bb = bias0;
    float* Cc = C0;
    if (MODE == 7) {
        int seg = n0 >> 10; nrel = n0 & 1023;
        Cc = (seg == 0) ? C0 : (seg == 1) ? C1 : C2;
        bb = (seg == 0) ? bias0 : (seg == 1) ? bias1 : bias2;
    }
    if (MODE == 8) {
        int seg = n0 >> 10; nrel = n0 & 1023;
        Cc = seg ? C1 : C0;
        bb = seg ? bias1 : bias0;
    }

    float* stg = sm;
#pragma unroll
    for (int fm = 0; fm < FM; fm++)
#pragma unroll
        for (int fn = 0; fn < FN; fn++)
            wmma::store_matrix_sync(stg + (wy * WTM + fm * 16) * STG_R + wx * WTN + fn * 16,
                                    cf[fm][fn], STG_R, wmma::mem_row_major);
    __syncthreads();

    constexpr int QPR = NT / 4;
#pragma unroll
    for (int p = 0; p < (128 * QPR) / 256; p++) {
        int idx = p * 256 + t;
        int rr = idx / QPR;
        int cq = (idx % QPR) * 4;
        float4 o = *(const float4*)&stg[rr * STG_R + cq];
        float vv[4] = {o.x, o.y, o.z, o.w};
#pragma unroll
        for (int c2 = 0; c2 < 4; c2++) {
            if (em == 1)            vv[c2] = rn32(vv[c2] + __ldg(&bb[nrel + cq + c2]));
            if (em == 2)            vv[c2] = rn32(fmaxf(vv[c2] + __ldg(&bb[n0 + cq + c2]), 0.f));
            if (em == 3)            vv[c2] += __ldg(&bb[n0 + cq + c2]);
            if (em == 5) {
                vv[c2] *= 0.125f;
                if (__ldg(&mask[(z >> 4) * LSEQ + n0 + cq + c2]) == 0) vv[c2] = -1e30f;
            }
            if (em == 6)            vv[c2] = rn32(vv[c2]);
        }
        o.x = vv[0]; o.y = vv[1]; o.z = vv[2]; o.w = vv[3];
        if (em == 3) {
            const float4 rv = *(const float4*)&Rres[(size_t)(m0 + rr) * ncols + n0 + cq];
            o.x += rv.x; o.y += rv.y; o.z += rv.z; o.w += rv.w;
            *(float4*)&Cc[(size_t)(m0 + rr) * ncols + n0 + cq] = o;
        } else if (em == 1) {
            int m = m0 + rr, b = m >> 11, l = m & 2047;
            int nr = nrel + cq, h = nr >> 6, d = nr & 63;
            *(float4*)&Cc[(((size_t)(b * NH + h)) * LSEQ + l) * HD + d] = o;
        } else if (em == 5) {
            *(float4*)&Cc[(size_t)z * LSEQ * LSEQ + (size_t)(m0 + rr) * LSEQ + n0 + cq] = o;
        } else if (em == 6) {
            int b = z >> 4, h = z & 15;
            *(float4*)&Cc[((size_t)(b * LSEQ + m0 + rr)) * HIDD + h * HD + n0 + cq] = o;
        } else { // em == 2
            *(float4*)&Cc[(size_t)(m0 + rr) * ncols + n0 + cq] = o;
        }
    }
}

// ---------------------------------------------------------------------------
// RN-round copy: 8 x 1M-float weights -> g_wt[0..8M), f1 -> [8M..12M),
// f2 -> [12M..16M), tgt -> g_tgtr, enc -> g_encr.  All in float4 units.
// ---------------------------------------------------------------------------
__global__ void __launch_bounds__(256)
roundcopy_k(const float4* s0, const float4* s1, const float4* s2, const float4* s3,
            const float4* s4, const float4* s5, const float4* s6, const float4* s7,
            const float4* f1, const float4* f2, const float4* tg, const float4* en,
            float4* wt, float4* tgtr, float4* encr)
{
    long long idx4 = (long long)blockIdx.x * 256 + threadIdx.x;
    const float4* src; float4* dst;
    if (idx4 < 2097152) {
        int wsel = (int)(idx4 >> 18);
        long long o = idx4 & 262143;
        const float4* s = (wsel == 0) ? s0 : (wsel == 1) ? s1 : (wsel == 2) ? s2 :
                          (wsel == 3) ? s3 : (wsel == 4) ? s4 : (wsel == 5) ? s5 :
                          (wsel == 6) ? s6 : s7;
        src = s + o; dst = wt + idx4;
    } else if (idx4 < 3145728) { src = f1 + (idx4 - 2097152); dst = wt + idx4; }
    else if (idx4 < 4194304)   { src = f2 + (idx4 - 3145728); dst = wt + idx4; }
    else if (idx4 < 5242880)   { long long o = idx4 - 4194304; src = tg + o; dst = tgtr + o; }
    else                       { long long o = idx4 - 5242880; src = en + o; dst = encr + o; }
    float4 v = *src;
    v.x = rn32(v.x); v.y = rn32(v.y); v.z = rn32(v.z); v.w = rn32(v.w);
    *dst = v;
}

// ---------------------------------------------------------------------------
__global__ void __launch_bounds__(256) softmax_k(float* __restrict__ S)
{
    float* p = S + (size_t)blockIdx.x * LSEQ;
    const int t = threadIdx.x;
    __shared__ float red[8];

    float v[8];
    float mx = -3.4e38f;
#pragma unroll
    for (int i = 0; i < 8; i++) { v[i] = p[t + 256 * i]; mx = fmaxf(mx, v[i]); }
#pragma unroll
    for (int o = 16; o; o >>= 1) mx = fmaxf(mx, __shfl_xor_sync(0xffffffffu, mx, o));
    if ((t & 31) == 0) red[t >> 5] = mx;
    __syncthreads();
    mx = red[0];
#pragma unroll
    for (int i = 1; i < 8; i++) mx = fmaxf(mx, red[i]);

    float s = 0.f;
#pragma unroll
    for (int i = 0; i < 8; i++) { v[i] = __expf(v[i] - mx); s += v[i]; }
#pragma unroll
    for (int o = 16; o; o >>= 1) s += __shfl_xor_sync(0xffffffffu, s, o);
    __syncthreads();
    if ((t & 31) == 0) red[t >> 5] = s;
    __syncthreads();
    s = 0.f;
#pragma unroll
    for (int i = 0; i < 8; i++) s += red[i];

    const float inv = 1.0f / s;
#pragma unroll
    for (int i = 0; i < 8; i++) p[t + 256 * i] = v[i] * inv;
}

// ---------------------------------------------------------------------------
// LayerNorm; writes full-precision Y and (optional) RN-rounded Yr.
// ---------------------------------------------------------------------------
__global__ void __launch_bounds__(256)
ln_k(const float* __restrict__ X, const float* __restrict__ gam,
     const float* __restrict__ bet, float* __restrict__ Y, float* __restrict__ Yr)
{
    const float* x = X + (size_t)blockIdx.x * HIDD;
    float*       y = Y + (size_t)blockIdx.x * HIDD;
    const int t = threadIdx.x;
    __shared__ float red[8];

    float v[4];
    float s = 0.f;
#pragma unroll
    for (int i = 0; i < 4; i++) { v[i] = x[t + 256 * i]; s += v[i]; }
#pragma unroll
    for (int o = 16; o; o >>= 1) s += __shfl_xor_sync(0xffffffffu, s, o);
    if ((t & 31) == 0) red[t >> 5] = s;
    __syncthreads();
    s = 0.f;
#pragma unroll
    for (int i = 0; i < 8; i++) s += red[i];
    const float mean = s * (1.0f / HIDD);

    float vs = 0.f;
#pragma unroll
    for (int i = 0; i < 4; i++) { float d = v[i] - mean; vs += d * d; }
#pragma unroll
    for (int o = 16; o; o >>= 1) vs += __shfl_xor_sync(0xffffffffu, vs, o);
    __syncthreads();
    if ((t & 31) == 0) red[t >> 5] = vs;
    __syncthreads();
    vs = 0.f;
#pragma unroll
    for (int i = 0; i < 8; i++) vs += red[i];
    const float inv = rsqrtf(vs * (1.0f / HIDD) + 1e-5f);

#pragma unroll
    for (int i = 0; i < 4; i++) {
        int c = t + 256 * i;
        float o = (v[i] - mean) * inv * gam[c] + bet[c];
        y[c] = o;
        if (Yr) Yr[(size_t)blockIdx.x * HIDD + c] = rn32(o);
    }
}

// ---------------------------------------------------------------------------
#define SMEM_D 206848   // 4 stages * (128*36 + 32*260) * 4B
#define SMEM_S 165888   // 3 stages * (128+256)*36*4B
#define SMEM_P 81408    // 3 stages * (128*36 + 32*68) * 4B

extern "C" void kernel_launch(void* const* d_in, const int* in_sizes, int n_in,
                              void* d_out, int out_size)
{
    const float* tgt    = (const float*)d_in[0];
    const float* enc    = (const float*)d_in[1];
    const int*   tmask  = (const int*)  d_in[2];
    const int*   smask  = (const int*)  d_in[3];
    const float* sa_wq  = (const float*)d_in[4],  *sa_bq = (const float*)d_in[5];
    const float* sa_wk  = (const float*)d_in[6],  *sa_bk = (const float*)d_in[7];
    const float* sa_wv  = (const float*)d_in[8],  *sa_bv = (const float*)d_in[9];
    const float* sa_wo  = (const float*)d_in[10], *sa_bo = (const float*)d_in[11];
    const float* ea_wq  = (const float*)d_in[12], *ea_bq = (const float*)d_in[13];
    const float* ea_wk  = (const float*)d_in[14], *ea_bk = (const float*)d_in[15];
    const float* ea_wv  = (const float*)d_in[16], *ea_bv = (const float*)d_in[17];
    const float* ea_wo  = (const float*)d_in[18], *ea_bo = (const float*)d_in[19];
    const float* ffn_w1 = (const float*)d_in[20], *ffn_b1 = (const float*)d_in[21];
    const float* ffn_w2 = (const float*)d_in[22], *ffn_b2 = (const float*)d_in[23];
    const float* ln1_g  = (const float*)d_in[24], *ln1_b = (const float*)d_in[25];
    const float* ln2_g  = (const float*)d_in[26], *ln2_b = (const float*)d_in[27];
    const float* ln3_g  = (const float*)d_in[28], *ln3_b = (const float*)d_in[29];

    float* out     = (float*)d_out;
    float* att_out = out + (size_t)BC * LSEQ * HIDD;

    float *q, *k, *v, *ao, *h, *hr, *ffn, *sc, *wt, *tgtr, *encr;
    cudaGetSymbolAddress((void**)&q,    g_q);
    cudaGetSymbolAddress((void**)&k,    g_k);
    cudaGetSymbolAddress((void**)&v,    g_v);
    cudaGetSymbolAddress((void**)&ao,   g_ao);
    cudaGetSymbolAddress((void**)&h,    g_h);
    cudaGetSymbolAddress((void**)&hr,   g_hr);
    cudaGetSymbolAddress((void**)&ffn,  g_ffn);
    cudaGetSymbolAddress((void**)&sc,   g_sc);
    cudaGetSymbolAddress((void**)&wt,   g_wt);
    cudaGetSymbolAddress((void**)&tgtr, g_tgtr);
    cudaGetSymbolAddress((void**)&encr, g_encr);

    const size_t M1 = 1024 * 1024;

    cudaFuncSetAttribute(tc_gemm<7,256,0,0,1,4>, cudaFuncAttributeMaxDynamicSharedMemorySize, SMEM_D);
    cudaFuncSetAttribute(tc_gemm<8,256,0,0,1,4>, cudaFuncAttributeMaxDynamicSharedMemorySize, SMEM_D);
    cudaFuncSetAttribute(tc_gemm<1,256,0,0,1,4>, cudaFuncAttributeMaxDynamicSharedMemorySize, SMEM_D);
    cudaFuncSetAttribute(tc_gemm<2,256,0,0,1,4>, cudaFuncAttributeMaxDynamicSharedMemorySize, SMEM_D);
    cudaFuncSetAttribute(tc_gemm<3,256,0,0,1,4>, cudaFuncAttributeMaxDynamicSharedMemorySize, SMEM_D);
    cudaFuncSetAttribute(tc_gemm<5,256,1,0,1,3>, cudaFuncAttributeMaxDynamicSharedMemorySize, SMEM_S);
    cudaFuncSetAttribute(tc_gemm<6,64,0,1,2,3>,  cudaFuncAttributeMaxDynamicSharedMemorySize, SMEM_P);

    // ---- RN-round all GEMM operand sources ----
    roundcopy_k<<<24576, 256>>>(
        (const float4*)sa_wq, (const float4*)sa_wk, (const float4*)sa_wv, (const float4*)sa_wo,
        (const float4*)ea_wq, (const float4*)ea_wk, (const float4*)ea_wv, (const float4*)ea_wo,
        (const float4*)ffn_w1, (const float4*)ffn_w2, (const float4*)tgt, (const float4*)enc,
        (float4*)wt, (float4*)tgtr, (float4*)encr);

    float* w_saq = wt + 0 * M1; float* w_sao = wt + 3 * M1;
    float* w_eaq = wt + 4 * M1; float* w_eak = wt + 5 * M1; float* w_eao = wt + 7 * M1;
    float* w_f1  = wt + 8 * M1; float* w_f2  = wt + 12 * M1;

    const dim3 gqkv(12, 32, 1);
    const dim3 gkv (8, 32, 1);
    const dim3 gp  (4, 32, 1);
    const dim3 gf1 (16, 32, 1);
    const dim3 gsc (8, 16, BC * NH);
    const dim3 gpv (1, 16, BC * NH);
    const long long ABq = (long long)LSEQ * HD;
    const long long ABs = (long long)LSEQ * LSEQ;

    // ---- self-attention ----
    tc_gemm<7,256,0,0,1,4><<<gqkv, 256, SMEM_D>>>(tgtr, w_saq, sa_bq, sa_bk, sa_bv, nullptr, nullptr,
                                                  q, k, v, 1024, 1024, 1024, 1024, 0, 0);
    tc_gemm<5,256,1,0,1,3><<<gsc, 256, SMEM_S>>>(q, k, nullptr, nullptr, nullptr, nullptr, tmask,
                                                 sc, nullptr, nullptr, 64, 64, 64, 2048, ABq, ABq);
    softmax_k<<<BC * NH * LSEQ, 256>>>(sc);
    tc_gemm<6,64,0,1,2,3><<<gpv, 256, SMEM_P>>>(sc, v, nullptr, nullptr, nullptr, nullptr, nullptr,
                                                ao, nullptr, nullptr, 2048, 2048, 64, 64, ABs, ABq);
    tc_gemm<3,256,0,0,1,4><<<gp, 256, SMEM_D>>>(ao, w_sao, sa_bo, nullptr, nullptr, tgt, nullptr,
                                                h, nullptr, nullptr, 1024, 1024, 1024, 1024, 0, 0);
    ln_k<<<MROWS, 256>>>(h, ln1_g, ln1_b, h, hr);

    // ---- cross-attention (probs straight into d_out region) ----
    tc_gemm<1,256,0,0,1,4><<<gp, 256, SMEM_D>>>(hr, w_eaq, ea_bq, nullptr, nullptr, nullptr, nullptr,
                                                q, nullptr, nullptr, 1024, 1024, 1024, 1024, 0, 0);
    tc_gemm<8,256,0,0,1,4><<<gkv, 256, SMEM_D>>>(encr, w_eak, ea_bk, ea_bv, nullptr, nullptr, nullptr,
                                                 k, v, nullptr, 1024, 1024, 1024, 1024, 0, 0);
    tc_gemm<5,256,1,0,1,3><<<gsc, 256, SMEM_S>>>(q, k, nullptr, nullptr, nullptr, nullptr, smask,
                                                 att_out, nullptr, nullptr, 64, 64, 64, 2048, ABq, ABq);
    softmax_k<<<BC * NH * LSEQ, 256>>>(att_out);
    tc_gemm<6,64,0,1,2,3><<<gpv, 256, SMEM_P>>>(att_out, v, nullptr, nullptr, nullptr, nullptr, nullptr,
                                                ao, nullptr, nullptr, 2048, 2048, 64, 64, ABs, ABq);
    tc_gemm<3,256,0,0,1,4><<<gp, 256, SMEM_D>>>(ao, w_eao, ea_bo, nullptr, nullptr, h, nullptr,
                                                h, nullptr, nullptr, 1024, 1024, 1024, 1024, 0, 0);
    ln_k<<<MROWS, 256>>>(h, ln2_g, ln2_b, h, hr);

    // ---- FFN ----
    tc_gemm<2,256,0,0,1,4><<<gf1, 256, SMEM_D>>>(hr, w_f1, ffn_b1, nullptr, nullptr, nullptr, nullptr,
                                                 ffn, nullptr, nullptr, 1024, 1024, 4096, 4096, 0, 0);
    tc_gemm<3,256,0,0,1,4><<<gp, 256, SMEM_D>>>(ffn, w_f2, ffn_b2, nullptr, nullptr, h, nullptr,
                                                h, nullptr, nullptr, 4096, 4096, 1024, 1024, 0, 0);
    ln_k<<<MROWS, 256>>>(h, ln3_g, ln3_b, out, nullptr);
}